// round 8
// baseline (speedup 1.0000x reference)
#include <cuda_runtime.h>
#include <cuda_bf16.h>
#include <math_constants.h>
#include <limits.h>

// Segment-max pooling, sorted ids (N rows x 32 ch -> M segments).
// float4 layout: one warp LDG.128 covers 4 rows (row_sub = lane>>3 selects the
// row, ch4 = lane&7 the float4 within the row). 16 feat LDGs per 64-row chunk
// instead of 64. Boundaries from a 64-bit ballot mask; segment flush combines
// the 4 row groups with an 8/16 shfl_xor butterfly and stores via 8 lanes
// (one STG.128 per segment). Rows before the warp's first boundary are loaded
// by nobody (skip) or polluted-and-discarded (resp=false at first flush).

#define CHUNK 64

typedef unsigned long long ull;
#define FULLM 0xFFFFFFFFu

__device__ __forceinline__ float4 fmax4(float4 a, float4 b) {
    a.x = fmaxf(a.x, b.x); a.y = fmaxf(a.y, b.y);
    a.z = fmaxf(a.z, b.z); a.w = fmaxf(a.w, b.w);
    return a;
}
__device__ __forceinline__ float4 neg4() {
    return make_float4(-CUDART_INF_F, -CUDART_INF_F,
                       -CUDART_INF_F, -CUDART_INF_F);
}
// max across the 4 row groups (xor lanes 8 and 16)
__device__ __forceinline__ float4 combine4(float4 t) {
    t.x = fmaxf(t.x, __shfl_xor_sync(FULLM, t.x, 8));
    t.y = fmaxf(t.y, __shfl_xor_sync(FULLM, t.y, 8));
    t.z = fmaxf(t.z, __shfl_xor_sync(FULLM, t.z, 8));
    t.w = fmaxf(t.w, __shfl_xor_sync(FULLM, t.w, 8));
    t.x = fmaxf(t.x, __shfl_xor_sync(FULLM, t.x, 16));
    t.y = fmaxf(t.y, __shfl_xor_sync(FULLM, t.y, 16));
    t.z = fmaxf(t.z, __shfl_xor_sync(FULLM, t.z, 16));
    t.w = fmaxf(t.w, __shfl_xor_sync(FULLM, t.w, 16));
    return t;
}

__global__ __launch_bounds__(256, 7) void seg_max_kernel(
    const float* __restrict__ feat,
    const int*   __restrict__ ids,
    float*       __restrict__ out,
    int N, int M)
{
    const int lane    = threadIdx.x & 31;
    const int warp    = blockIdx.x * (blockDim.x >> 5) + (threadIdx.x >> 5);
    const int row_sub = lane >> 3;     // which of 4 rows in a group-load
    const int ch4     = lane & 7;      // which float4 within the row

    const long long r0 = (long long)warp * CHUNK;
    if (r0 >= N) return;
    const int nrows = (int)(((long long)N - r0 < CHUNK) ? (N - r0) : CHUNK);

    const float4* f4   = (const float4*)feat;
    float4*       out4 = (float4*)out;
    const float4  z4   = make_float4(0.f, 0.f, 0.f, 0.f);

    // Coalesced chunk ids + prefetch of the 32 ids after the chunk.
    int id_lo = (lane < nrows)      ? ids[r0 + lane]      : 0;
    int id_hi = (32 + lane < nrows) ? ids[r0 + 32 + lane] : 0;
    int idn0  = (r0 + CHUNK + lane < N) ? ids[r0 + CHUNK + lane] : INT_MAX;
    const int prev_id = (r0 > 0) ? ids[r0 - 1] : -1;

    int    cur  = prev_id;
    bool   resp = false;
    float4 m    = neg4();

// flush/accumulate one 4-row group 'v' whose boundary bits are 'gbits'
// (bit b => row gbase+b starts a new segment)
#define PROC_GROUP(v, gbits, gbase)                                        \
    {                                                                      \
        unsigned gb = (gbits);                                             \
        if (gb == 0u) {                                                    \
            m = fmax4(m, v);                                               \
        } else {                                                           \
            int seg_start = 0;                                             \
            do {                                                           \
                int b = __ffs(gb) - 1; gb &= gb - 1u;                      \
                int i = (gbase) + b;                                       \
                int nid = __shfl_sync(FULLM, (i < 32) ? id_lo : id_hi,     \
                                      i & 31);                             \
                bool in = (row_sub >= seg_start) && (row_sub < b);         \
                float4 t = combine4(fmax4(m, in ? v : neg4()));            \
                if (resp) {                                                \
                    if (row_sub == 0) {                                    \
                        out4[(long long)cur * 8 + ch4] = t;                \
                        for (int g = cur + 1; g < nid; ++g)                \
                            out4[(long long)g * 8 + ch4] = z4;             \
                    }                                                      \
                }                                                          \
                cur = nid; m = neg4(); seg_start = b; resp = true;         \
            } while (gb);                                                  \
            m = fmax4(m, (row_sub >= seg_start) ? v : neg4());             \
        }                                                                  \
    }

    if (nrows == CHUNK) {
        // 64-bit boundary mask: bit i set iff ids[r0+i] != ids[r0+i-1].
        int p = __shfl_up_sync(FULLM, id_lo, 1);
        if (lane == 0) p = prev_id;
        unsigned mlo = __ballot_sync(FULLM, id_lo != p);
        int s = __shfl_sync(FULLM, id_lo, 31);
        p = __shfl_up_sync(FULLM, id_hi, 1);
        if (lane == 0) p = s;
        unsigned mhi = __ballot_sync(FULLM, id_hi != p);
        const ull bmask = (ull)mlo | ((ull)mhi << 32);
        const int i0 = bmask ? (__ffsll((long long)bmask) - 1) : CHUNK;

        #pragma unroll
        for (int base = 0; base < CHUNK; base += 8) {
            if (base + 8 <= i0) continue;    // uniform: rows owned upstream

            // two 4-row group loads (8 rows, 2 x LDG.128)
            float4 v0 = __ldcs(&f4[(r0 + base     + row_sub) * 8 + ch4]);
            float4 v1 = __ldcs(&f4[(r0 + base + 4 + row_sub) * 8 + ch4]);

            const unsigned bb = (unsigned)(bmask >> base) & 0xFFu;
            if (bb == 0u) {
                m = fmax4(m, fmax4(v0, v1));
            } else {
                PROC_GROUP(v0, bb & 0xFu, base);
                PROC_GROUP(v1, (bb >> 4) & 0xFu, base + 4);
            }
        }
    } else {
        // Ragged last chunk: row-at-a-time (only lanes row_sub==0 load).
        for (int i = 0; i < nrows; ++i) {
            int id = __shfl_sync(FULLM, (i < 32) ? id_lo : id_hi, i & 31);
            if (id != cur) {
                if (resp) {
                    float4 t = combine4(m);
                    if (row_sub == 0) {
                        out4[(long long)cur * 8 + ch4] = t;
                        for (int g = cur + 1; g < id; ++g)
                            out4[(long long)g * 8 + ch4] = z4;
                    }
                }
                cur = id; m = neg4(); resp = true;
            }
            float4 v = neg4();
            if (row_sub == 0) v = f4[(r0 + i) * 8 + ch4];
            m = fmax4(m, v);
        }
    }

    // Finish the last segment we own: it may continue past the chunk end.
    long long r = r0 + nrows;
    if (resp) {
        bool first = (nrows == CHUNK);
        while (r < N) {                        // uniform condition
            long long rl = r + lane;
            int idn = first ? idn0 : ((rl < N) ? ids[rl] : INT_MAX);
            first = false;
            unsigned diff = __ballot_sync(FULLM, idn != cur);
            int k = diff ? (__ffs(diff) - 1) : 32;   // continuation rows
            for (int tt = 0; tt < k; tt += 4) {
                if (tt + row_sub < k) {
                    float4 vt = __ldcs(&f4[(r + tt + row_sub) * 8 + ch4]);
                    m = fmax4(m, vt);
                }
            }
            r += k;
            if (k < 32) break;
        }
        float4 t = combine4(m);
        int next_id = (r < N) ? ids[r] : M;
        if (row_sub == 0) {
            out4[(long long)cur * 8 + ch4] = t;
            for (int g = cur + 1; g < next_id; ++g)
                out4[(long long)g * 8 + ch4] = z4;
        }
    }

    // Leading gap: segments before ids[0] are empty.
    if (r0 == 0 && row_sub == 0) {
        int first_id = ids[0];
        for (int g = 0; g < first_id; ++g)
            out4[(long long)g * 8 + ch4] = z4;
    }
#undef PROC_GROUP
}

extern "C" void kernel_launch(void* const* d_in, const int* in_sizes, int n_in,
                              void* d_out, int out_size) {
    const float* feat = (const float*)d_in[0];
    const int*   ids  = (const int*)d_in[1];
    float*       out  = (float*)d_out;

    const int N = in_sizes[1];
    const int M = out_size / 32;

    const int warps   = (N + CHUNK - 1) / CHUNK;
    const int threads = 256;
    const int blocks  = (warps * 32 + threads - 1) / threads;

    seg_max_kernel<<<blocks, threads>>>(feat, ids, out, N, M);
}

// round 9
// speedup vs baseline: 1.1123x; 1.1123x over previous
#include <cuda_runtime.h>
#include <cuda_bf16.h>
#include <math_constants.h>
#include <limits.h>

// Segment-max pooling, sorted ids (N rows x 32 ch -> M segments).
// One warp owns CHUNK=64 rows; lane = channel (scalar LDG.32: optimal L1
// wavefront cost). Boundaries precomputed as a 64-bit ballot mask.
// Skip-start at BATCH granularity only: full batches before the warp's first
// boundary are skipped (uniform branch); the partial batch is loaded
// unconditionally -- polluted rows are discarded at the first flush since
// resp==false. No per-lane selects anywhere in the load path.
// All indexing in 32-bit (N*32 < 2^31). Tail ids prefetched. regs pinned.

#define CHUNK 64
#define BATCH 8

typedef unsigned long long ull;

__global__ __launch_bounds__(256, 8) void seg_max_kernel(
    const float* __restrict__ feat,
    const int*   __restrict__ ids,
    float*       __restrict__ out,
    int N, int M)
{
    const unsigned FULL = 0xFFFFFFFFu;
    const int lane = threadIdx.x & 31;
    const int warp = blockIdx.x * (blockDim.x >> 5) + (threadIdx.x >> 5);

    const int r0 = warp * CHUNK;               // < 4M, fits int
    if (r0 >= N) return;
    const int nrows = (N - r0 < CHUNK) ? (N - r0) : CHUNK;

    // Coalesced chunk ids + prefetch of the 32 ids after the chunk.
    int id_lo = (lane < nrows)      ? ids[r0 + lane]      : 0;
    int id_hi = (32 + lane < nrows) ? ids[r0 + 32 + lane] : 0;
    int idn0  = (r0 + CHUNK + lane < N) ? ids[r0 + CHUNK + lane] : INT_MAX;
    const int prev_id = (r0 > 0) ? ids[r0 - 1] : -1;

    int   cur  = prev_id;
    bool  resp = false;
    float m    = -CUDART_INF_F;

    const float* fptr = feat + (unsigned)r0 * 32u + (unsigned)lane;

    if (nrows == CHUNK) {
        // 64-bit boundary mask: bit i set iff ids[r0+i] != ids[r0+i-1].
        int p = __shfl_up_sync(FULL, id_lo, 1);
        if (lane == 0) p = prev_id;
        unsigned mlo = __ballot_sync(FULL, id_lo != p);

        int s = __shfl_sync(FULL, id_lo, 31);
        p = __shfl_up_sync(FULL, id_hi, 1);
        if (lane == 0) p = s;
        unsigned mhi = __ballot_sync(FULL, id_hi != p);

        const ull bmask = (ull)mlo | ((ull)mhi << 32);
        // First row we own; full batches before it are skipped entirely.
        const int i0 = bmask ? (__ffsll((long long)bmask) - 1) : CHUNK;

        #pragma unroll
        for (int base = 0; base < CHUNK; base += BATCH) {
            if (base + BATCH <= i0) continue;   // uniform: fully skipped

            // Unconditional batch of independent LDG.32 (pre-i0 rows in the
            // partial batch pollute m harmlessly: discarded at first flush).
            float v[BATCH];
            #pragma unroll
            for (int j = 0; j < BATCH; ++j)
                v[j] = __ldcs(&fptr[(base + j) * 32]);

            const unsigned bb = (unsigned)(bmask >> base) & 0xFFu;
            if (bb == 0u) {                     // uniform: no boundary
                float a = fmaxf(v[0], v[1]);
                float b = fmaxf(v[2], v[3]);
                float c = fmaxf(v[4], v[5]);
                float d = fmaxf(v[6], v[7]);
                m = fmaxf(m, fmaxf(fmaxf(a, b), fmaxf(c, d)));
            } else {
                #pragma unroll
                for (int j = 0; j < BATCH; ++j) {
                    if ((bb >> j) & 1u) {       // uniform (mask bit)
                        const int i = base + j;
                        int nid = __shfl_sync(FULL, (i < 32) ? id_lo : id_hi,
                                              i & 31);
                        if (resp) {
                            out[cur * 32 + lane] = m;
                            for (int g = cur + 1; g < nid; ++g)
                                out[g * 32 + lane] = 0.0f;
                        }
                        cur  = nid;
                        m    = -CUDART_INF_F;
                        resp = true;
                    }
                    m = fmaxf(m, v[j]);
                }
            }
        }
    } else {
        // Ragged last chunk: scalar path (one warp in the grid).
        for (int i = 0; i < nrows; ++i) {
            int id = __shfl_sync(FULL, (i < 32) ? id_lo : id_hi, i & 31);
            if (id != cur) {
                if (resp) {
                    out[cur * 32 + lane] = m;
                    for (int g = cur + 1; g < id; ++g)
                        out[g * 32 + lane] = 0.0f;
                }
                cur  = id;
                m    = -CUDART_INF_F;
                resp = true;
            }
            m = fmaxf(m, fptr[i * 32]);
        }
    }

    // Finish the last segment we own: it may continue past the chunk end.
    int r = r0 + nrows;
    if (resp) {
        bool first = (nrows == CHUNK);
        while (r < N) {                         // uniform condition
            int rl = r + lane;
            int idn = first ? idn0 : ((rl < N) ? ids[rl] : INT_MAX);
            first = false;
            unsigned diff = __ballot_sync(FULL, idn != cur);
            int k = diff ? (__ffs(diff) - 1) : 32;   // continuation rows
            for (int j = 0; j < k; ++j)              // independent loads
                m = fmaxf(m, __ldcs(&feat[(unsigned)(r + j) * 32u + lane]));
            r += k;
            if (k < 32) break;
        }
        out[cur * 32 + lane] = m;
        int next_id = (r < N) ? ids[r] : M;
        for (int g = cur + 1; g < next_id; ++g)
            out[g * 32 + lane] = 0.0f;
    }

    // Leading gap: segments before ids[0] are empty.
    if (r0 == 0) {
        int first_id = ids[0];
        for (int g = 0; g < first_id; ++g)
            out[g * 32 + lane] = 0.0f;
    }
}

extern "C" void kernel_launch(void* const* d_in, const int* in_sizes, int n_in,
                              void* d_out, int out_size) {
    const float* feat = (const float*)d_in[0];
    const int*   ids  = (const int*)d_in[1];
    float*       out  = (float*)d_out;

    const int N = in_sizes[1];
    const int M = out_size / 32;

    const int warps   = (N + CHUNK - 1) / CHUNK;
    const int threads = 256;
    const int blocks  = (warps * 32 + threads - 1) / threads;

    seg_max_kernel<<<blocks, threads>>>(feat, ids, out, N, M);
}